// round 1
// baseline (speedup 1.0000x reference)
#include <cuda_runtime.h>
#include <cuda_bf16.h>

// BuzzLoss: B=8192 rows, T=1024 cols.
// score[b] = sum_t conf[b,t] * excl_cumprod(1-conf)[b,t] * acc[b,t]
//          + (1 - sum_t conf[b,t]*excl_cumprod[b,t]) * acc[b,T-1]
// out = -mean_b score[b]
//
// One 256-thread CTA per row; each thread handles 4 contiguous elements
// (float4). Product-scan via shfl within warp + 8-warp smem scan.

#define FULL_MASK 0xFFFFFFFFu

__global__ void buzz_zero_kernel(float* out) {
    out[0] = 0.0f;
}

__global__ __launch_bounds__(256, 8)
void buzz_loss_kernel(const float* __restrict__ conf,
                      const float* __restrict__ acc,
                      float* __restrict__ out,
                      int B) {
    const int row = blockIdx.x;
    const int tid = threadIdx.x;
    const int lane = tid & 31;
    const int wid = tid >> 5;

    __shared__ float s_warp_prod[8];
    __shared__ float s_s1[8];
    __shared__ float s_s2[8];
    __shared__ float s_acc_last;

    const float4* c4p = reinterpret_cast<const float4*>(conf + (size_t)row * 1024);
    const float4* a4p = reinterpret_cast<const float4*>(acc  + (size_t)row * 1024);

    const float4 c = c4p[tid];
    const float4 a = a4p[tid];

    // local (1-c) factors
    const float q0 = 1.0f - c.x;
    const float q1 = 1.0f - c.y;
    const float q2 = 1.0f - c.z;
    const float q3 = 1.0f - c.w;

    // thread-local product of all 4
    float p = q0 * q1 * q2 * q3;

    // warp inclusive product-scan of per-thread products
    float inc = p;
    #pragma unroll
    for (int d = 1; d < 32; d <<= 1) {
        float v = __shfl_up_sync(FULL_MASK, inc, d);
        if (lane >= d) inc *= v;
    }
    // exclusive prefix within warp
    float excl = __shfl_up_sync(FULL_MASK, inc, 1);
    if (lane == 0) excl = 1.0f;

    // warp totals -> smem
    if (lane == 31) s_warp_prod[wid] = inc;
    if (tid == 255) s_acc_last = a.w;
    __syncthreads();

    // exclusive product of preceding warps (8 warps: tiny serial loop)
    float wpref = 1.0f;
    #pragma unroll
    for (int w = 0; w < 8; w++) {
        if (w < wid) wpref *= s_warp_prod[w];
    }

    // exclusive cumprod just before this thread's first element
    float E = wpref * excl;

    // buzz probs for the 4 local elements
    const float b0 = c.x * E;
    const float b1 = c.y * (E * q0);
    const float b2 = c.z * (E * q0 * q1);
    const float b3 = c.w * (E * q0 * q1 * q2);

    float s1 = b0 * a.x + b1 * a.y + b2 * a.z + b3 * a.w;  // sum buzz*acc
    float s2 = b0 + b1 + b2 + b3;                          // sum buzz

    // warp reduce
    #pragma unroll
    for (int d = 16; d >= 1; d >>= 1) {
        s1 += __shfl_down_sync(FULL_MASK, s1, d);
        s2 += __shfl_down_sync(FULL_MASK, s2, d);
    }
    if (lane == 0) { s_s1[wid] = s1; s_s2[wid] = s2; }
    __syncthreads();

    if (wid == 0) {
        float t1 = (lane < 8) ? s_s1[lane] : 0.0f;
        float t2 = (lane < 8) ? s_s2[lane] : 0.0f;
        #pragma unroll
        for (int d = 4; d >= 1; d >>= 1) {
            t1 += __shfl_down_sync(FULL_MASK, t1, d);
            t2 += __shfl_down_sync(FULL_MASK, t2, d);
        }
        if (lane == 0) {
            float score = t1 + (1.0f - t2) * s_acc_last;
            atomicAdd(out, -score / (float)B);
        }
    }
}

extern "C" void kernel_launch(void* const* d_in, const int* in_sizes, int n_in,
                              void* d_out, int out_size) {
    const float* conf = (const float*)d_in[0];
    const float* acc  = (const float*)d_in[1];
    float* out = (float*)d_out;

    const int total = in_sizes[0];
    const int T = 1024;
    const int B = total / T;

    buzz_zero_kernel<<<1, 1>>>(out);
    buzz_loss_kernel<<<B, 256>>>(conf, acc, out, B);
}